// round 7
// baseline (speedup 1.0000x reference)
#include <cuda_runtime.h>
#include <cstdint>

#define NMODES 32
#define NLEN   8192
#define NHALF  4096
#define JPAD   4224          // padded j-extent (covers 33 inverse tiles of 128)
#define NROWS  2048          // 32 batch * 64 channels
#define SPLITK 32
#define CH     32            // forward k-chunk
#define NCHUNK 129           // ceil(4097/32)

typedef unsigned long long ull;

// Scratch (device globals; no runtime allocation allowed)
__device__ float2 g_table[NMODES * JPAD];            // (cos, -sin), ~1.1 MB
__device__ float2 g_xpart[SPLITK * NROWS * NMODES];  // forward split-K partials, 16 MB
__device__ float2 g_xsum[NROWS * NMODES];            // reduced X[b,i,m]
__device__ float2 g_coef[NROWS * NMODES];            // (c*Re, c*Im) after einsum
__device__ float2 g_wpack[NMODES * 64 * 64];         // weights repacked [m][i][o]

__device__ __forceinline__ ull fma2(ull a, ull b, ull c) {
    ull d;
    asm("fma.rn.f32x2 %0, %1, %2, %3;" : "=l"(d) : "l"(a), "l"(b), "l"(c));
    return d;
}
__device__ __forceinline__ ull ldu(const float2* p) {
    return *reinterpret_cast<const ull*>(p);
}
__device__ __forceinline__ float2 u2f(ull v) {
    float2 f;
    f.x = __uint_as_float((unsigned)v);
    f.y = __uint_as_float((unsigned)(v >> 32));
    return f;
}

// ---------------------------------------------------------------------------
// Kernel 1: trig table  T[m][j] = (cos(2*pi*m*j/N), -sin(...)), j in [0,4096],
// zero-padded to JPAD. Exact int reduction mod 8192 -> sincospif.
// ---------------------------------------------------------------------------
__global__ void init_table_kernel() {
    int idx = blockIdx.x * blockDim.x + threadIdx.x;
    if (idx >= NMODES * JPAD) return;
    int m = idx / JPAD;
    int j = idx - m * JPAD;
    float2 v;
    if (j > NHALF) {
        v = make_float2(0.f, 0.f);
    } else {
        int p = (m * j) & (NLEN - 1);            // theta/pi = p/4096, exact
        float a = (float)p * (1.0f / 4096.0f);
        float s, c;
        sincospif(a, &s, &c);
        v = make_float2(c, -s);
    }
    g_table[idx] = v;
}

// ---------------------------------------------------------------------------
// Kernel 2: forward folded-DFT projection, split-K.
// Block: 128 threads = tx(8 cols) x ty(16 rows). Thread tile: 8 rows x 4 cols.
// Block covers 128 rows x 32 mode-cols (each col = packed (Re,Im) f32x2).
// ---------------------------------------------------------------------------
__global__ __launch_bounds__(128) void fwd_kernel(const float* __restrict__ x) {
    __shared__ float2 eos[128 * 33];   // [row][jj], stride 33
    __shared__ float2 trigs[CH * 33];  // [jj][m],  stride 33
    const int rb = blockIdx.x;         // 0..15 row blocks of 128
    const int s  = blockIdx.y;         // split-K slice
    const int t  = threadIdx.x;
    const int tx = t & 7;              // col group
    const int ty = t >> 3;             // row group (0..15)
    const int row0 = rb * 128;
    const int lane_jj = t & 31;        // fill: lane -> jj
    const int gsel    = t >> 5;        // fill: row group 0..3

    ull acc[8][4];
#pragma unroll
    for (int u = 0; u < 8; u++)
#pragma unroll
        for (int v = 0; v < 4; v++) acc[u][v] = 0ull;

    for (int ch = s; ch < NCHUNK; ch += SPLITK) {
        const int j0 = ch * CH;
        // eos fill: each warp handles rows gsel*32 + rr, lanes cover jj
        {
            const int j  = j0 + lane_jj;
            float a = 0.f, b = 0.f;
            const bool mid  = (j >= 1) && (j < NHALF);
            const bool is0  = (j == 0);
            const bool isH  = (j == NHALF);
#pragma unroll 8
            for (int rr = 0; rr < 32; rr++) {
                const int r = gsel * 32 + rr;
                const float* xr = x + (size_t)(row0 + r) * NLEN;
                float e, o;
                if (mid)       { a = xr[j]; b = xr[NLEN - j]; e = a + b; o = a - b; }
                else if (is0)  { e = xr[0];      o = 0.f; }
                else if (isH)  { e = xr[NHALF];  o = 0.f; }
                else           { e = 0.f;        o = 0.f; }
                eos[r * 33 + lane_jj] = make_float2(e, o);
            }
        }
        // trig fill: 32jj x 32m = 1024 entries, 8 per thread
#pragma unroll
        for (int q = 0; q < 8; q++) {
            int idx = q * 128 + t;
            int m = idx >> 5, jj = idx & 31;
            trigs[jj * 33 + m] = g_table[m * JPAD + j0 + jj];
        }
        __syncthreads();
#pragma unroll 8
        for (int jj = 0; jj < CH; jj++) {
            ull tg[4];
#pragma unroll
            for (int v = 0; v < 4; v++) tg[v] = ldu(&trigs[jj * 33 + tx + 8 * v]);
#pragma unroll
            for (int u = 0; u < 8; u++) {
                ull e = ldu(&eos[(ty + 16 * u) * 33 + jj]);
                acc[u][0] = fma2(e, tg[0], acc[u][0]);
                acc[u][1] = fma2(e, tg[1], acc[u][1]);
                acc[u][2] = fma2(e, tg[2], acc[u][2]);
                acc[u][3] = fma2(e, tg[3], acc[u][3]);
            }
        }
        __syncthreads();
    }
#pragma unroll
    for (int u = 0; u < 8; u++)
#pragma unroll
        for (int v = 0; v < 4; v++)
            g_xpart[((size_t)s * NROWS + row0 + ty + 16 * u) * NMODES + tx + 8 * v]
                = u2f(acc[u][v]);
}

// ---------------------------------------------------------------------------
// Kernel 3: split-K reduction  g_xsum = sum_s g_xpart[s]
// ---------------------------------------------------------------------------
__global__ __launch_bounds__(256) void reduce_kernel() {
    int e = blockIdx.x * 256 + threadIdx.x;     // 0..65535
    float2 sum = make_float2(0.f, 0.f);
#pragma unroll
    for (int p = 0; p < SPLITK; p++) {
        float2 v = g_xpart[(size_t)p * (NROWS * NMODES) + e];
        sum.x += v.x; sum.y += v.y;
    }
    g_xsum[e] = sum;
}

// ---------------------------------------------------------------------------
// Kernel 4: repack weights -> [m][i][o] interleaved (re,im)
// ---------------------------------------------------------------------------
__global__ void repack_kernel(const float* __restrict__ wr, const float* __restrict__ wi) {
    int idx = blockIdx.x * blockDim.x + threadIdx.x;
    if (idx >= 64 * 64 * NMODES) return;
    int m = idx & 31;
    int o = (idx >> 5) & 63;
    int i = idx >> 11;
    g_wpack[(m * 64 + i) * 64 + o] = make_float2(wr[idx], wi[idx]);
}

// ---------------------------------------------------------------------------
// Kernel 5: complex einsum over Cin + irfft scaling.
// Grid (m=32, bg=4); block 256 = o(64) x bh(4); thread does 2 batches.
// ---------------------------------------------------------------------------
__global__ __launch_bounds__(256) void einsum_kernel() {
    __shared__ float2 Xs[8 * 64];            // [bl][i] for 8 batches
    const int m = blockIdx.x, bg = blockIdx.y;
    const int t = threadIdx.x;
    const int o = t & 63, bh = t >> 6;       // bh 0..3
    // fill Xs
#pragma unroll
    for (int q = 0; q < 2; q++) {
        int idx = q * 256 + t;
        int bl = idx >> 6, i = idx & 63;
        Xs[bl * 64 + i] = g_xsum[((bg * 8 + bl) * 64 + i) * NMODES + m];
    }
    __syncthreads();
    float a0r = 0.f, a0i = 0.f, a1r = 0.f, a1i = 0.f;
#pragma unroll 8
    for (int i = 0; i < 64; i++) {
        float2 w  = g_wpack[(m * 64 + i) * 64 + o];
        float2 X0 = Xs[(bh * 2) * 64 + i];
        float2 X1 = Xs[(bh * 2 + 1) * 64 + i];
        a0r = fmaf(X0.x, w.x, a0r); a0r = fmaf(-X0.y, w.y, a0r);
        a0i = fmaf(X0.x, w.y, a0i); a0i = fmaf( X0.y, w.x, a0i);
        a1r = fmaf(X1.x, w.x, a1r); a1r = fmaf(-X1.y, w.y, a1r);
        a1i = fmaf(X1.x, w.y, a1i); a1i = fmaf( X1.y, w.x, a1i);
    }
    float c = (m == 0 ? 1.f : 2.f) * (1.f / (float)NLEN);
    int b0 = bg * 8 + bh * 2, b1 = b0 + 1;
    g_coef[((size_t)b0 * 64 + o) * NMODES + m] = make_float2(c * a0r, c * a0i);
    g_coef[((size_t)b1 * 64 + o) * NMODES + m] = make_float2(c * a1r, c * a1i);
}

// ---------------------------------------------------------------------------
// Kernel 6: inverse folded irfft, K=32 GEMM.
// Block: 128 threads = tx(32 j) x ty(4 rows); thread tile 8 rows x 4 j.
// Block covers 32 rows x 128 j.  out[j]=P+Q, out[N-j]=P-Q.
// ---------------------------------------------------------------------------
__global__ __launch_bounds__(128) void inv_kernel(float* __restrict__ out) {
    __shared__ float2 coefs[32 * 33];   // [r][m]
    __shared__ float2 trigs[32 * 129];  // [m][jj]
    const int rb = blockIdx.x, jb = blockIdx.y;
    const int t = threadIdx.x;
    const int tx = t & 31, ty = t >> 5;  // ty 0..3
    const int row0 = rb * 32, j0 = jb * 128;

#pragma unroll
    for (int q = 0; q < 8; q++) {
        int idx = q * 128 + t;
        int r = idx >> 5, m = idx & 31;
        coefs[r * 33 + m] = g_coef[(row0 + r) * NMODES + m];
    }
#pragma unroll
    for (int q = 0; q < 32; q++) {
        int idx = q * 128 + t;
        int m = idx >> 7, jj = idx & 127;
        trigs[m * 129 + jj] = g_table[m * JPAD + j0 + jj];
    }
    __syncthreads();

    ull acc[8][4];
#pragma unroll
    for (int u = 0; u < 8; u++)
#pragma unroll
        for (int v = 0; v < 4; v++) acc[u][v] = 0ull;

#pragma unroll 8
    for (int m = 0; m < NMODES; m++) {
        ull g[4];
#pragma unroll
        for (int v = 0; v < 4; v++) g[v] = ldu(&trigs[m * 129 + tx + 32 * v]);
#pragma unroll
        for (int u = 0; u < 8; u++) {
            ull c = ldu(&coefs[(ty + 4 * u) * 33 + m]);
            acc[u][0] = fma2(c, g[0], acc[u][0]);
            acc[u][1] = fma2(c, g[1], acc[u][1]);
            acc[u][2] = fma2(c, g[2], acc[u][2]);
            acc[u][3] = fma2(c, g[3], acc[u][3]);
        }
    }

#pragma unroll
    for (int u = 0; u < 8; u++) {
        int r = row0 + ty + 4 * u;
        float* orow = out + (size_t)r * NLEN;
#pragma unroll
        for (int v = 0; v < 4; v++) {
            int j = j0 + tx + 32 * v;
            float2 pq = u2f(acc[u][v]);
            if (j <= NHALF)           orow[j] = pq.x + pq.y;           // out[j]   = P+Q
            if (j >= 1 && j < NHALF)  orow[NLEN - j] = pq.x - pq.y;    // out[N-j] = P-Q
        }
    }
}

// ---------------------------------------------------------------------------
extern "C" void kernel_launch(void* const* d_in, const int* in_sizes, int n_in,
                              void* d_out, int out_size) {
    const float* x  = (const float*)d_in[0];
    const float* wr = (const float*)d_in[1];
    const float* wi = (const float*)d_in[2];
    float* out = (float*)d_out;

    init_table_kernel<<<(NMODES * JPAD + 255) / 256, 256>>>();
    repack_kernel<<<(64 * 64 * NMODES + 255) / 256, 256>>>(wr, wi);
    fwd_kernel<<<dim3(16, SPLITK), 128>>>(x);
    reduce_kernel<<<(NROWS * NMODES) / 256, 256>>>();
    einsum_kernel<<<dim3(32, 4), 256>>>();
    inv_kernel<<<dim3(64, 33), 128>>>(out);
}

// round 8
// speedup vs baseline: 1.0840x; 1.0840x over previous
#include <cuda_runtime.h>
#include <cstdint>

#define NMODES 32
#define NLEN   8192
#define NHALF  4096
#define JPAD   4224          // padded j-extent (covers 33 inverse tiles of 128)
#define NROWS  2048          // 32 batch * 64 channels
#define SPLITK 16
#define CH     32            // forward k-chunk
#define NCHUNK 129           // ceil(4097/32)

// Scratch (device globals; no runtime allocation allowed)
__device__ float2 g_table[NMODES * JPAD];            // (cos, -sin), ~1.1 MB
__device__ float2 g_xpart[SPLITK * NROWS * NMODES];  // forward split-K partials, 8 MB
__device__ float2 g_coef[NROWS * NMODES];            // (c*Re, c*Im) after einsum
__device__ float2 g_wpack[NMODES * 64 * 64];         // weights repacked [m][i][o]

// ---------------------------------------------------------------------------
// Kernel 1: trig table  T[m][j] = (cos(2*pi*m*j/N), -sin(...)), j in [0,4096],
// zero-padded to JPAD. Exact int reduction mod 8192 -> sincospif.
// ---------------------------------------------------------------------------
__global__ void init_table_kernel() {
    int idx = blockIdx.x * blockDim.x + threadIdx.x;
    if (idx >= NMODES * JPAD) return;
    int m = idx / JPAD;
    int j = idx - m * JPAD;
    float2 v;
    if (j > NHALF) {
        v = make_float2(0.f, 0.f);
    } else {
        int p = (m * j) & (NLEN - 1);            // theta/pi = p/4096, exact
        float a = (float)p * (1.0f / 4096.0f);
        float s, c;
        sincospif(a, &s, &c);
        v = make_float2(c, -s);
    }
    g_table[idx] = v;
}

// ---------------------------------------------------------------------------
// Kernel 2: repack weights -> [m][i][o] interleaved (re,im)
// ---------------------------------------------------------------------------
__global__ void repack_kernel(const float* __restrict__ wr, const float* __restrict__ wi) {
    int idx = blockIdx.x * blockDim.x + threadIdx.x;
    if (idx >= 64 * 64 * NMODES) return;
    int m = idx & 31;
    int o = (idx >> 5) & 63;
    int i = idx >> 11;
    g_wpack[(m * 64 + i) * 64 + o] = make_float2(wr[idx], wi[idx]);
}

// ---------------------------------------------------------------------------
// Kernel 3: forward folded-DFT projection, split-K, SCALAR FFMA.
// Block: 256 threads = tx(8 col-groups) x ty(32 row-groups).
// Thread tile: 2 rows x 4 cols. Block covers 64 rows x 32 modes.
//   Re[m] += e * cos,  Im[m] += o * (-sin)
// ---------------------------------------------------------------------------
__global__ __launch_bounds__(256) void fwd_kernel(const float* __restrict__ x) {
    __shared__ float2 eos[64 * 33];    // [row][jj], stride 33  (e,o)
    __shared__ float2 trigs[CH * 33];  // [jj][m],  stride 33   (cos,-sin)
    const int rb = blockIdx.x;         // 0..31 row blocks of 64
    const int s  = blockIdx.y;         // split-K slice 0..15
    const int t  = threadIdx.x;
    const int tx = t & 7;              // col group
    const int ty = t >> 3;             // row group (0..31)
    const int row0 = rb * 64;
    const int lane_jj = t & 31;        // fill: lane -> jj
    const int wsel    = t >> 5;        // fill: warp -> 8-row group

    float accRe[2][4], accIm[2][4];
#pragma unroll
    for (int u = 0; u < 2; u++)
#pragma unroll
        for (int v = 0; v < 4; v++) { accRe[u][v] = 0.f; accIm[u][v] = 0.f; }

    for (int ch = s; ch < NCHUNK; ch += SPLITK) {
        const int j0 = ch * CH;
        // eos fill: warp wsel handles rows wsel*8..wsel*8+7, lanes cover jj
        {
            const int j  = j0 + lane_jj;
            const bool mid  = (j >= 1) && (j < NHALF);
            const bool is0  = (j == 0);
            const bool isH  = (j == NHALF);
#pragma unroll
            for (int rr = 0; rr < 8; rr++) {
                const int r = wsel * 8 + rr;
                const float* xr = x + (size_t)(row0 + r) * NLEN;
                float e, o;
                if (mid)       { float a = xr[j], b = xr[NLEN - j]; e = a + b; o = a - b; }
                else if (is0)  { e = xr[0];      o = 0.f; }
                else if (isH)  { e = xr[NHALF];  o = 0.f; }
                else           { e = 0.f;        o = 0.f; }
                eos[r * 33 + lane_jj] = make_float2(e, o);
            }
        }
        // trig fill: 32jj x 32m = 1024 entries, 4 per thread
#pragma unroll
        for (int q = 0; q < 4; q++) {
            int idx = q * 256 + t;
            int m = idx >> 5, jj = idx & 31;
            trigs[jj * 33 + m] = g_table[m * JPAD + j0 + jj];
        }
        __syncthreads();
#pragma unroll 4
        for (int jj = 0; jj < CH; jj++) {
            float2 tg[4];
#pragma unroll
            for (int v = 0; v < 4; v++) tg[v] = trigs[jj * 33 + tx + 8 * v];
#pragma unroll
            for (int u = 0; u < 2; u++) {
                float2 eo = eos[(ty + 32 * u) * 33 + jj];
#pragma unroll
                for (int v = 0; v < 4; v++) {
                    accRe[u][v] = fmaf(eo.x, tg[v].x, accRe[u][v]);
                    accIm[u][v] = fmaf(eo.y, tg[v].y, accIm[u][v]);
                }
            }
        }
        __syncthreads();
    }
#pragma unroll
    for (int u = 0; u < 2; u++)
#pragma unroll
        for (int v = 0; v < 4; v++)
            g_xpart[((size_t)s * NROWS + row0 + ty + 32 * u) * NMODES + tx + 8 * v]
                = make_float2(accRe[u][v], accIm[u][v]);
}

// ---------------------------------------------------------------------------
// Kernel 4: fused split-K reduce + complex einsum over Cin + irfft scaling.
// Grid (m=32, bg=8); block 256 = o(64) x bh(4); thread does 1 batch.
// coef[b,o,m] = c_m * Sum_i X[b,i,m] * w[i,o,m];  c_0=1/N, else 2/N
// ---------------------------------------------------------------------------
__global__ __launch_bounds__(256) void einsum_kernel() {
    __shared__ float2 Xs[4 * 64];            // [bl][i] for 4 batches
    const int m = blockIdx.x, bg = blockIdx.y;
    const int t = threadIdx.x;
    const int o = t & 63, bh = t >> 6;       // bh 0..3
    // fill Xs with split-K sum: thread t handles (bl = t>>6, i = t&63)
    {
        int bl = t >> 6, i = t & 63;
        size_t base = (size_t)((bg * 4 + bl) * 64 + i) * NMODES + m;
        float sr = 0.f, si = 0.f;
#pragma unroll
        for (int p = 0; p < SPLITK; p++) {
            float2 v = g_xpart[(size_t)p * (NROWS * NMODES) + base];
            sr += v.x; si += v.y;
        }
        Xs[bl * 64 + i] = make_float2(sr, si);
    }
    __syncthreads();
    float ar = 0.f, ai = 0.f;
#pragma unroll 8
    for (int i = 0; i < 64; i++) {
        float2 w = g_wpack[(m * 64 + i) * 64 + o];
        float2 X = Xs[bh * 64 + i];
        ar = fmaf(X.x, w.x, ar);
        ar = fmaf(-X.y, w.y, ar);
        ai = fmaf(X.x, w.y, ai);
        ai = fmaf(X.y, w.x, ai);
    }
    float c = (m == 0 ? 1.f : 2.f) * (1.f / (float)NLEN);
    int b = bg * 4 + bh;
    g_coef[((size_t)b * 64 + o) * NMODES + m] = make_float2(c * ar, c * ai);
}

// ---------------------------------------------------------------------------
// Kernel 5: inverse folded irfft, K=32 GEMM, SCALAR FFMA.
// Block: 256 threads = tx(32 j) x ty(8 rows); thread tile 4 rows x 4 j.
// Block covers 32 rows x 128 j.
//   P += cA*cos,  Q += cB*(-sin);  out[j]=P+Q, out[N-j]=P-Q.
// ---------------------------------------------------------------------------
__global__ __launch_bounds__(256) void inv_kernel(float* __restrict__ out) {
    __shared__ float2 coefs[32 * 33];   // [r][m]  (cA, cB)
    __shared__ float2 trigs[32 * 129];  // [m][jj] (cos, -sin)
    const int rb = blockIdx.x, jb = blockIdx.y;
    const int t = threadIdx.x;
    const int tx = t & 31, ty = t >> 5;  // ty 0..7
    const int row0 = rb * 32, j0 = jb * 128;

#pragma unroll
    for (int q = 0; q < 4; q++) {
        int idx = q * 256 + t;
        int r = idx >> 5, m = idx & 31;
        coefs[r * 33 + m] = g_coef[(row0 + r) * NMODES + m];
    }
#pragma unroll
    for (int q = 0; q < 16; q++) {
        int idx = q * 256 + t;
        int m = idx >> 7, jj = idx & 127;
        trigs[m * 129 + jj] = g_table[m * JPAD + j0 + jj];
    }
    __syncthreads();

    float P[4][4], Q[4][4];
#pragma unroll
    for (int u = 0; u < 4; u++)
#pragma unroll
        for (int v = 0; v < 4; v++) { P[u][v] = 0.f; Q[u][v] = 0.f; }

#pragma unroll 4
    for (int m = 0; m < NMODES; m++) {
        float2 tg[4];
#pragma unroll
        for (int v = 0; v < 4; v++) tg[v] = trigs[m * 129 + tx + 32 * v];
#pragma unroll
        for (int u = 0; u < 4; u++) {
            float2 cf = coefs[(ty + 8 * u) * 33 + m];
#pragma unroll
            for (int v = 0; v < 4; v++) {
                P[u][v] = fmaf(cf.x, tg[v].x, P[u][v]);
                Q[u][v] = fmaf(cf.y, tg[v].y, Q[u][v]);
            }
        }
    }

#pragma unroll
    for (int u = 0; u < 4; u++) {
        int r = row0 + ty + 8 * u;
        float* orow = out + (size_t)r * NLEN;
#pragma unroll
        for (int v = 0; v < 4; v++) {
            int j = j0 + tx + 32 * v;
            if (j <= NHALF)           orow[j] = P[u][v] + Q[u][v];        // out[j]
            if (j >= 1 && j < NHALF)  orow[NLEN - j] = P[u][v] - Q[u][v]; // out[N-j]
        }
    }
}

// ---------------------------------------------------------------------------
extern "C" void kernel_launch(void* const* d_in, const int* in_sizes, int n_in,
                              void* d_out, int out_size) {
    const float* x  = (const float*)d_in[0];
    const float* wr = (const float*)d_in[1];
    const float* wi = (const float*)d_in[2];
    float* out = (float*)d_out;

    init_table_kernel<<<(NMODES * JPAD + 255) / 256, 256>>>();
    repack_kernel<<<(64 * 64 * NMODES + 255) / 256, 256>>>(wr, wi);
    fwd_kernel<<<dim3(32, SPLITK), 256>>>(x);
    einsum_kernel<<<dim3(32, 8), 256>>>();
    inv_kernel<<<dim3(64, 33), 256>>>(out);
}

// round 16
// speedup vs baseline: 1.3557x; 1.2506x over previous
#include <cuda_runtime.h>
#include <cstdint>

#define NMODES 32
#define NLEN   8192
#define NHALF  4096
#define JPAD   4224          // padded j-extent (covers 33 inverse tiles of 128)
#define NROWS  2048          // 32 batch * 64 channels
#define SPLITK 16
#define CH     32            // forward k-chunk
#define NCHUNK 129           // ceil(4097/32)

// Scratch (device globals; no runtime allocation allowed)
__device__ float2 g_table[NMODES * JPAD];            // (cos, -sin), ~1.1 MB
__device__ float2 g_xpart[SPLITK * NMODES * NROWS];  // split-K partials, [s][m][row], 8 MB
__device__ float2 g_coef[NROWS * NMODES];            // (c*Re, c*Im) after einsum
__device__ float2 g_wpack[NMODES * 64 * 64];         // weights repacked [m][i][o]

// ---------------------------------------------------------------------------
// Kernel 1: trig table  T[m][j] = (cos(2*pi*m*j/N), -sin(...)), j in [0,4096],
// zero-padded to JPAD. Exact int reduction mod 8192 -> sincospif.
// ---------------------------------------------------------------------------
__global__ void init_table_kernel() {
    int idx = blockIdx.x * blockDim.x + threadIdx.x;
    if (idx >= NMODES * JPAD) return;
    int m = idx / JPAD;
    int j = idx - m * JPAD;
    float2 v;
    if (j > NHALF) {
        v = make_float2(0.f, 0.f);
    } else {
        int p = (m * j) & (NLEN - 1);            // theta/pi = p/4096, exact
        float a = (float)p * (1.0f / 4096.0f);
        float s, c;
        sincospif(a, &s, &c);
        v = make_float2(c, -s);
    }
    g_table[idx] = v;
}

// ---------------------------------------------------------------------------
// Kernel 2: repack weights -> [m][i][o] interleaved (re,im)
// ---------------------------------------------------------------------------
__global__ void repack_kernel(const float* __restrict__ wr, const float* __restrict__ wi) {
    int idx = blockIdx.x * blockDim.x + threadIdx.x;
    if (idx >= 64 * 64 * NMODES) return;
    int m = idx & 31;
    int o = (idx >> 5) & 63;
    int i = idx >> 11;
    g_wpack[(m * 64 + i) * 64 + o] = make_float2(wr[idx], wi[idx]);
}

// ---------------------------------------------------------------------------
// Kernel 2.5: no-op spacer. Purpose: shift fwd_kernel to the 4th launch slot
// so the fixed-index ncu capture (-s 5 -c 1) profiles fwd_kernel this round.
// ---------------------------------------------------------------------------
__global__ void nop_kernel() {}

// ---------------------------------------------------------------------------
// Kernel 3: forward folded-DFT projection, split-K, SCALAR FFMA,
// register-pipelined fill: next chunk's global loads are issued right after
// the barrier and consumed one mainloop later (hides ~600cyc DRAM latency
// under the ~2000cyc compute phase).
// Block: 256 threads = tx(8 col-groups) x ty(32 row-groups).
// Thread tile: 2 rows x 4 cols. Block covers 64 rows x 32 modes.
//   Re[m] += e * cos,  Im[m] += o * (-sin);  e=x[j]+x[N-j], o=x[j]-x[N-j]
// ---------------------------------------------------------------------------
__global__ __launch_bounds__(256) void fwd_kernel(const float* __restrict__ x) {
    __shared__ float2 eos[64 * 33];    // [row][jj], stride 33  (e,o)
    __shared__ float2 trigs[CH * 33];  // [jj][m],  stride 33   (cos,-sin)
    const int rb = blockIdx.x;         // 0..31 row blocks of 64
    const int s  = blockIdx.y;         // split-K slice 0..15
    const int t  = threadIdx.x;
    const int tx = t & 7;              // col group
    const int ty = t >> 3;             // row group (0..31)
    const int row0 = rb * 64;
    const int lane_jj = t & 31;        // fill: lane -> jj
    const int wsel    = t >> 5;        // fill: warp -> 8-row group

    float accRe[2][4], accIm[2][4];
#pragma unroll
    for (int u = 0; u < 2; u++)
#pragma unroll
        for (int v = 0; v < 4; v++) { accRe[u][v] = 0.f; accIm[u][v] = 0.f; }

    // prefetch registers for the eos fill (8 rows x (a,b)) and trig fill (4 f2)
    float pa[8], pb[8];
    bool  pmid = false;
    float2 ptg[4];

    // --- prefetch helper (expanded inline twice below) ---
    // chunk ch: j = ch*CH + lane_jj;  a=x[j](or edge), b=x[N-j] (0 if !mid)

    // prologue: prefetch first chunk (ch = s)
    {
        const int j  = s * CH + lane_jj;
        const bool mid = (j >= 1) && (j < NHALF);
        const bool is0 = (j == 0);
        const bool isH = (j == NHALF);
        pmid = mid;
#pragma unroll
        for (int rr = 0; rr < 8; rr++) {
            const float* xr = x + (size_t)(row0 + wsel * 8 + rr) * NLEN;
            float av = 0.f, bv = 0.f;
            if (mid)      { av = xr[j]; bv = xr[NLEN - j]; }
            else if (is0) { av = xr[0]; }
            else if (isH) { av = xr[NHALF]; }
            pa[rr] = av; pb[rr] = bv;
        }
#pragma unroll
        for (int q = 0; q < 4; q++) {
            int idx = q * 256 + t;
            int m = idx >> 5, jj = idx & 31;
            ptg[q] = g_table[m * JPAD + s * CH + jj];
        }
    }

    for (int ch = s; ch < NCHUNK; ch += SPLITK) {
        // ---- stage prefetched data into smem ----
#pragma unroll
        for (int rr = 0; rr < 8; rr++) {
            float e = pa[rr] + pb[rr];                    // bv=0 on edges
            float o = pmid ? (pa[rr] - pb[rr]) : 0.f;
            eos[(wsel * 8 + rr) * 33 + lane_jj] = make_float2(e, o);
        }
#pragma unroll
        for (int q = 0; q < 4; q++) {
            int idx = q * 256 + t;
            int m = idx >> 5, jj = idx & 31;
            trigs[jj * 33 + m] = ptg[q];
        }
        __syncthreads();

        // ---- issue prefetch for NEXT chunk (latency hidden under compute) ----
        const int chn = ch + SPLITK;
        if (chn < NCHUNK) {
            const int j  = chn * CH + lane_jj;
            const bool mid = (j >= 1) && (j < NHALF);
            const bool is0 = (j == 0);
            const bool isH = (j == NHALF);
            pmid = mid;
#pragma unroll
            for (int rr = 0; rr < 8; rr++) {
                const float* xr = x + (size_t)(row0 + wsel * 8 + rr) * NLEN;
                float av = 0.f, bv = 0.f;
                if (mid)      { av = xr[j]; bv = xr[NLEN - j]; }
                else if (is0) { av = xr[0]; }
                else if (isH) { av = xr[NHALF]; }
                pa[rr] = av; pb[rr] = bv;
            }
#pragma unroll
            for (int q = 0; q < 4; q++) {
                int idx = q * 256 + t;
                int m = idx >> 5, jj = idx & 31;
                ptg[q] = g_table[m * JPAD + chn * CH + jj];
            }
        }

        // ---- mainloop over this chunk ----
#pragma unroll 4
        for (int jj = 0; jj < CH; jj++) {
            float2 tg[4];
#pragma unroll
            for (int v = 0; v < 4; v++) tg[v] = trigs[jj * 33 + tx + 8 * v];
#pragma unroll
            for (int u = 0; u < 2; u++) {
                float2 eo = eos[(ty + 32 * u) * 33 + jj];
#pragma unroll
                for (int v = 0; v < 4; v++) {
                    accRe[u][v] = fmaf(eo.x, tg[v].x, accRe[u][v]);
                    accIm[u][v] = fmaf(eo.y, tg[v].y, accIm[u][v]);
                }
            }
        }
        __syncthreads();   // protect smem before next stage overwrites
    }
    // store partials in [s][mode][row] layout (coalesced einsum reads)
#pragma unroll
    for (int u = 0; u < 2; u++)
#pragma unroll
        for (int v = 0; v < 4; v++)
            g_xpart[((size_t)s * NMODES + tx + 8 * v) * NROWS + row0 + ty + 32 * u]
                = make_float2(accRe[u][v], accIm[u][v]);
}

// ---------------------------------------------------------------------------
// Kernel 4: fused split-K reduce + complex einsum over Cin + irfft scaling.
// Grid (m=32, bg=8); block 256 = o(64) x bh(4); thread does 1 batch.
// coef[b,o,m] = c_m * Sum_i X[b,i,m] * w[i,o,m];  c_0=1/N, else 2/N
// ---------------------------------------------------------------------------
__global__ __launch_bounds__(256) void einsum_kernel() {
    __shared__ float2 Xs[4 * 64];            // [bl][i] for 4 batches
    const int m = blockIdx.x, bg = blockIdx.y;
    const int t = threadIdx.x;
    const int o = t & 63, bh = t >> 6;       // bh 0..3
    // fill Xs with split-K sum: thread t handles (bl = t>>6, i = t&63)
    // [s][m][row] layout -> lanes read consecutive rows -> coalesced, MLP=SPLITK
    {
        int bl = t >> 6, i = t & 63;
        int row = (bg * 4 + bl) * 64 + i;
        float sr = 0.f, si = 0.f;
#pragma unroll
        for (int p = 0; p < SPLITK; p++) {
            float2 v = g_xpart[((size_t)p * NMODES + m) * NROWS + row];
            sr += v.x; si += v.y;
        }
        Xs[bl * 64 + i] = make_float2(sr, si);
    }
    __syncthreads();
    float ar = 0.f, ai = 0.f;
#pragma unroll 8
    for (int i = 0; i < 64; i++) {
        float2 w = g_wpack[(m * 64 + i) * 64 + o];
        float2 X = Xs[bh * 64 + i];
        ar = fmaf(X.x, w.x, ar);
        ar = fmaf(-X.y, w.y, ar);
        ai = fmaf(X.x, w.y, ai);
        ai = fmaf(X.y, w.x, ai);
    }
    float c = (m == 0 ? 1.f : 2.f) * (1.f / (float)NLEN);
    int b = bg * 4 + bh;
    g_coef[((size_t)b * 64 + o) * NMODES + m] = make_float2(c * ar, c * ai);
}

// ---------------------------------------------------------------------------
// Kernel 5: inverse folded irfft, K=32 GEMM, SCALAR FFMA.
// Block: 256 threads = tx(32 j) x ty(8 rows); thread tile 4 rows x 4 j.
// Block covers 32 rows x 128 j.  Mainloop is FFMA-bound (tg LDS conflict-free,
// cf fully warp-broadcast).
//   P += cA*cos,  Q += cB*(-sin);  out[j]=P+Q, out[N-j]=P-Q.
// ---------------------------------------------------------------------------
__global__ __launch_bounds__(256) void inv_kernel(float* __restrict__ out) {
    __shared__ float2 coefs[32 * 33];   // [r][m]  (cA, cB)
    __shared__ float2 trigs[32 * 129];  // [m][jj] (cos, -sin)
    const int rb = blockIdx.x, jb = blockIdx.y;
    const int t = threadIdx.x;
    const int tx = t & 31, ty = t >> 5;  // ty 0..7
    const int row0 = rb * 32, j0 = jb * 128;

#pragma unroll
    for (int q = 0; q < 4; q++) {
        int idx = q * 256 + t;
        int r = idx >> 5, m = idx & 31;
        coefs[r * 33 + m] = g_coef[(row0 + r) * NMODES + m];
    }
#pragma unroll
    for (int q = 0; q < 16; q++) {
        int idx = q * 256 + t;
        int m = idx >> 7, jj = idx & 127;
        trigs[m * 129 + jj] = g_table[m * JPAD + j0 + jj];
    }
    __syncthreads();

    float P[4][4], Q[4][4];
#pragma unroll
    for (int u = 0; u < 4; u++)
#pragma unroll
        for (int v = 0; v < 4; v++) { P[u][v] = 0.f; Q[u][v] = 0.f; }

#pragma unroll 4
    for (int m = 0; m < NMODES; m++) {
        float2 tg[4];
#pragma unroll
        for (int v = 0; v < 4; v++) tg[v] = trigs[m * 129 + tx + 32 * v];
#pragma unroll
        for (int u = 0; u < 4; u++) {
            float2 cf = coefs[(ty + 8 * u) * 33 + m];
#pragma unroll
            for (int v = 0; v < 4; v++) {
                P[u][v] = fmaf(cf.x, tg[v].x, P[u][v]);
                Q[u][v] = fmaf(cf.y, tg[v].y, Q[u][v]);
            }
        }
    }

#pragma unroll
    for (int u = 0; u < 4; u++) {
        int r = row0 + ty + 8 * u;
        float* orow = out + (size_t)r * NLEN;
#pragma unroll
        for (int v = 0; v < 4; v++) {
            int j = j0 + tx + 32 * v;
            if (j <= NHALF)           orow[j] = P[u][v] + Q[u][v];        // out[j]
            if (j >= 1 && j < NHALF)  orow[NLEN - j] = P[u][v] - Q[u][v]; // out[N-j]
        }
    }
}

// ---------------------------------------------------------------------------
extern "C" void kernel_launch(void* const* d_in, const int* in_sizes, int n_in,
                              void* d_out, int out_size) {
    const float* x  = (const float*)d_in[0];
    const float* wr = (const float*)d_in[1];
    const float* wi = (const float*)d_in[2];
    float* out = (float*)d_out;

    init_table_kernel<<<(NMODES * JPAD + 255) / 256, 256>>>();   // launch 1
    repack_kernel<<<(64 * 64 * NMODES + 255) / 256, 256>>>(wr, wi); // launch 2
    nop_kernel<<<1, 32>>>();                                     // launch 3 (spacer)
    fwd_kernel<<<dim3(32, SPLITK), 256>>>(x);                    // launch 4 -> profiled
    einsum_kernel<<<dim3(32, 8), 256>>>();                       // launch 5
    inv_kernel<<<dim3(64, 33), 256>>>(out);                      // launch 6
}